// round 2
// baseline (speedup 1.0000x reference)
#include <cuda_runtime.h>
#include <math.h>

// Problem constants
#define H  512
#define E  321
#define CC 321
#define T  96
#define P  96
#define B  512
#define G4 2048   // 4*H

// ---------------- scratch (device globals; no allocation allowed) ----------
__device__ float g_xT[(size_t)T * B * E];     // x_enc transposed to (T,B,E)
__device__ float g_pre[(size_t)T * B * G4];   // precomputed x@Wih'^T (interleaved)
__device__ float g_ys[(size_t)T * B * H];     // encoder layer0 outputs
__device__ float g_state[6 * B * H];          // h0a,h0b,c0,h1a,h1b,c1
__device__ float g_inp[B * E];                // decoder initial input

// interleaved weights: row (j*4+g) = original row (g*H+j)
__device__ float g_eWih0[G4 * E];
__device__ float g_eWhh0[G4 * H];
__device__ float g_eWih1[G4 * H];
__device__ float g_eWhh1[G4 * H];
__device__ float g_dWih0[G4 * E];
__device__ float g_dWhh0[G4 * H];
__device__ float g_dWih1[G4 * H];
__device__ float g_dWhh1[G4 * H];
__device__ float g_eB0[G4], g_eB1[G4], g_dB0[G4], g_dB1[G4];

// ---------------- weight transform kernels ----------------------------------
__global__ void interleave_w_kernel(const float* __restrict__ src,
                                    float* __restrict__ dst, int K)
{
    size_t idx = (size_t)blockIdx.x * blockDim.x + threadIdx.x;
    size_t total = (size_t)G4 * K;
    if (idx >= total) return;
    int np = (int)(idx / K);
    int k  = (int)(idx % K);
    int j = np >> 2, g = np & 3;
    dst[idx] = src[((size_t)(g * H + j)) * K + k];
}

__global__ void combine_bias_kernel(const float* __restrict__ bih,
                                    const float* __restrict__ bhh,
                                    float* __restrict__ dst)
{
    int n = blockIdx.x * blockDim.x + threadIdx.x;
    if (n >= G4) return;
    int j = n >> 2, g = n & 3;
    dst[n] = bih[g * H + j] + bhh[g * H + j];
}

// ---------------- small helper kernels --------------------------------------
__global__ void zero_kernel(float* p, int n) {
    int i = blockIdx.x * blockDim.x + threadIdx.x;
    if (i < n) p[i] = 0.f;
}

__global__ void transpose_bt_kernel(const float* __restrict__ in, float* __restrict__ out) {
    size_t i = (size_t)blockIdx.x * blockDim.x + threadIdx.x;
    size_t total = (size_t)B * T * E;
    if (i >= total) return;
    size_t e = i % E;
    size_t t = (i / E) % T;
    size_t b = i / ((size_t)E * T);
    out[(t * B + b) * E + e] = in[i];
}

__global__ void copy_last_kernel(const float* __restrict__ x, float* __restrict__ out) {
    int i = blockIdx.x * blockDim.x + threadIdx.x;
    if (i >= B * E) return;
    int b = i / E, e = i % E;
    out[i] = x[(size_t)b * T * E + (size_t)(T - 1) * E + e];
}

// ---------------- fused GEMM (+ optional dual-A, + LSTM epilogue) -----------
__device__ __forceinline__ float sigmf(float x) { return 1.f / (1.f + __expf(-x)); }

// C[m,n] = sum_k A1[m,k]*W1[n,k] (+ A2*W2) ; epilogue per EPI.
// EPI=0: Cout[m,n] = acc + bias[n]            (plain GEMM, bias optional)
// EPI=1: interleaved-gate LSTM cell update: each thread owns 4 consecutive
//        columns = (i,f,g,o) of one hidden unit. Updates c in place, writes
//        h to hout (ping-pong buffer), optional ys copy.
template<int BM, int BN, int MR, int EPI>
__global__ __launch_bounds__((BM / MR) * (BN / 4))
void gemm_fused(float* __restrict__ Cout, int ldc,
                const float* __restrict__ A1, int lda1, int K1,
                const float* __restrict__ W1,
                const float* __restrict__ A2, int lda2, int K2,
                const float* __restrict__ W2,
                const float* __restrict__ bias,
                const float* __restrict__ pre,   // EPI=1: M x G4, interleaved
                float* __restrict__ cst,         // EPI=1: B x H (in-place)
                float* __restrict__ hout,        // EPI=1: B x H
                float* __restrict__ ysout,       // EPI=1: optional B x H
                int M, int N)
{
    constexpr int BK = 16;
    constexpr int TCN = BN / 4;
    constexpr int THREADS = (BM / MR) * TCN;
    constexpr int LA = (BM * BK) / THREADS;
    constexpr int LB = (BN * BK) / THREADS;

    __shared__ float As[2][BK][BM];
    __shared__ float Ws[2][BK][BN];

    const int bm = blockIdx.y * BM;
    const int bn = blockIdx.x * BN;
    const int tid = threadIdx.x;
    const int tr = tid / TCN;
    const int tc = tid % TCN;

    float acc[MR][4];
#pragma unroll
    for (int i = 0; i < MR; ++i)
#pragma unroll
        for (int j = 0; j < 4; ++j) acc[i][j] = 0.f;

    float ra[LA], rb[LB];

    for (int phase = 0; phase < 2; ++phase) {
        const float* A = phase ? A2 : A1;
        const float* W = phase ? W2 : W1;
        const int K   = phase ? K2 : K1;
        const int lda = phase ? lda2 : lda1;
        if (A == nullptr) continue;
        const int nk = (K + BK - 1) / BK;

        // load first tile into buffer 0
#pragma unroll
        for (int i = 0; i < LA; ++i) {
            int l = tid + i * THREADS;
            int m = l / BK, k = l % BK;
            float v = 0.f;
            if (k < K) v = A[(size_t)(bm + m) * lda + k];
            As[0][k][m] = v;
        }
#pragma unroll
        for (int i = 0; i < LB; ++i) {
            int l = tid + i * THREADS;
            int n = l / BK, k = l % BK;
            float v = 0.f;
            if (bn + n < N && k < K) v = W[(size_t)(bn + n) * K + k];
            Ws[0][k][n] = v;
        }
        __syncthreads();

        int buf = 0;
        for (int it = 0; it < nk; ++it) {
            const int k0n = (it + 1) * BK;
            if (it + 1 < nk) {
#pragma unroll
                for (int i = 0; i < LA; ++i) {
                    int l = tid + i * THREADS;
                    int m = l / BK, k = l % BK;
                    float v = 0.f;
                    if (k0n + k < K) v = A[(size_t)(bm + m) * lda + k0n + k];
                    ra[i] = v;
                }
#pragma unroll
                for (int i = 0; i < LB; ++i) {
                    int l = tid + i * THREADS;
                    int n = l / BK, k = l % BK;
                    float v = 0.f;
                    if (bn + n < N && k0n + k < K) v = W[(size_t)(bn + n) * K + k0n + k];
                    rb[i] = v;
                }
            }

#pragma unroll
            for (int kk = 0; kk < BK; ++kk) {
                float av[MR];
#pragma unroll
                for (int u = 0; u < MR; u += 4) {
                    float4 a4 = *(const float4*)&As[buf][kk][tr * MR + u];
                    av[u] = a4.x; av[u + 1] = a4.y; av[u + 2] = a4.z; av[u + 3] = a4.w;
                }
                float4 w4 = *(const float4*)&Ws[buf][kk][tc * 4];
                float wv[4] = {w4.x, w4.y, w4.z, w4.w};
#pragma unroll
                for (int i = 0; i < MR; ++i)
#pragma unroll
                    for (int j = 0; j < 4; ++j)
                        acc[i][j] += av[i] * wv[j];
            }

            if (it + 1 < nk) {
#pragma unroll
                for (int i = 0; i < LA; ++i) {
                    int l = tid + i * THREADS;
                    int m = l / BK, k = l % BK;
                    As[buf ^ 1][k][m] = ra[i];
                }
#pragma unroll
                for (int i = 0; i < LB; ++i) {
                    int l = tid + i * THREADS;
                    int n = l / BK, k = l % BK;
                    Ws[buf ^ 1][k][n] = rb[i];
                }
                __syncthreads();
                buf ^= 1;
            }
        }
        __syncthreads();  // before next phase reuses smem
    }

    if (EPI == 0) {
#pragma unroll
        for (int i = 0; i < MR; ++i) {
            int gm = bm + tr * MR + i;
            if (gm >= M) continue;
#pragma unroll
            for (int j = 0; j < 4; ++j) {
                int gn = bn + tc * 4 + j;
                if (gn < N) {
                    float v = acc[i][j];
                    if (bias) v += bias[gn];
                    Cout[(size_t)gm * ldc + gn] = v;
                }
            }
        }
    } else {
        const int nb = bn + tc * 4;      // first of 4 gate columns
        const int jh = (bn >> 2) + tc;   // hidden unit index
        const float b0 = bias[nb + 0], b1 = bias[nb + 1];
        const float b2 = bias[nb + 2], b3 = bias[nb + 3];
#pragma unroll
        for (int i = 0; i < MR; ++i) {
            const int gm = bm + tr * MR + i;
            float gi = acc[i][0] + b0;
            float gf = acc[i][1] + b1;
            float gg = acc[i][2] + b2;
            float go = acc[i][3] + b3;
            if (pre) {
                const float* p = &pre[(size_t)gm * G4 + nb];
                gi += p[0]; gf += p[1]; gg += p[2]; go += p[3];
            }
            const size_t ci = (size_t)gm * H + jh;
            float cv = sigmf(gf) * cst[ci] + sigmf(gi) * tanhf(gg);
            float hv = sigmf(go) * tanhf(cv);
            cst[ci] = cv;
            hout[ci] = hv;
            if (ysout) ysout[ci] = hv;
        }
    }
}

// ---------------- launch helpers ---------------------------------------------
static inline void launch_plain(float* Cp, int ldc,
                                const float* A, int lda, int K, const float* W,
                                const float* bias, int M, int N, bool small)
{
    if (small) {
        dim3 grid((N + 31) / 32, (M + 31) / 32);
        gemm_fused<32, 32, 4, 0><<<grid, 64>>>(Cp, ldc, A, lda, K, W,
                                               nullptr, 0, 0, nullptr,
                                               bias, nullptr, nullptr, nullptr, nullptr, M, N);
    } else {
        dim3 grid((N + 63) / 64, (M + 63) / 64);
        gemm_fused<64, 64, 8, 0><<<grid, 128>>>(Cp, ldc, A, lda, K, W,
                                                nullptr, 0, 0, nullptr,
                                                bias, nullptr, nullptr, nullptr, nullptr, M, N);
    }
}

static inline void launch_lstm(const float* A1, int lda1, int K1, const float* W1,
                               const float* A2, int lda2, int K2, const float* W2,
                               const float* bias, const float* pre,
                               float* cst, float* hout, float* ysout)
{
    dim3 grid(G4 / 64, B / 64);
    gemm_fused<64, 64, 8, 1><<<grid, 128>>>(nullptr, 0, A1, lda1, K1, W1,
                                            A2, lda2, K2, W2,
                                            bias, pre, cst, hout, ysout, B, G4);
}

// ---------------- entry -------------------------------------------------------
extern "C" void kernel_launch(void* const* d_in, const int* in_sizes, int n_in,
                              void* d_out, int out_size)
{
    const float* x_enc  = (const float*)d_in[0];
    const float* e_Wih0 = (const float*)d_in[4];
    const float* e_Whh0 = (const float*)d_in[5];
    const float* e_bih0 = (const float*)d_in[6];
    const float* e_bhh0 = (const float*)d_in[7];
    const float* e_Wih1 = (const float*)d_in[8];
    const float* e_Whh1 = (const float*)d_in[9];
    const float* e_bih1 = (const float*)d_in[10];
    const float* e_bhh1 = (const float*)d_in[11];
    const float* d_Wih0 = (const float*)d_in[12];
    const float* d_Whh0 = (const float*)d_in[13];
    const float* d_bih0 = (const float*)d_in[14];
    const float* d_bhh0 = (const float*)d_in[15];
    const float* d_Wih1 = (const float*)d_in[16];
    const float* d_Whh1 = (const float*)d_in[17];
    const float* d_bih1 = (const float*)d_in[18];
    const float* d_bhh1 = (const float*)d_in[19];
    const float* fc_W   = (const float*)d_in[20];
    const float* fc_b   = (const float*)d_in[21];
    float* out = (float*)d_out;

    float *xT, *pre, *ys, *st, *inp0;
    float *eWih0, *eWhh0, *eWih1, *eWhh1, *dWih0, *dWhh0, *dWih1, *dWhh1;
    float *eB0, *eB1, *dB0, *dB1;
    cudaGetSymbolAddress((void**)&xT,    g_xT);
    cudaGetSymbolAddress((void**)&pre,   g_pre);
    cudaGetSymbolAddress((void**)&ys,    g_ys);
    cudaGetSymbolAddress((void**)&st,    g_state);
    cudaGetSymbolAddress((void**)&inp0,  g_inp);
    cudaGetSymbolAddress((void**)&eWih0, g_eWih0);
    cudaGetSymbolAddress((void**)&eWhh0, g_eWhh0);
    cudaGetSymbolAddress((void**)&eWih1, g_eWih1);
    cudaGetSymbolAddress((void**)&eWhh1, g_eWhh1);
    cudaGetSymbolAddress((void**)&dWih0, g_dWih0);
    cudaGetSymbolAddress((void**)&dWhh0, g_dWhh0);
    cudaGetSymbolAddress((void**)&dWih1, g_dWih1);
    cudaGetSymbolAddress((void**)&dWhh1, g_dWhh1);
    cudaGetSymbolAddress((void**)&eB0,   g_eB0);
    cudaGetSymbolAddress((void**)&eB1,   g_eB1);
    cudaGetSymbolAddress((void**)&dB0,   g_dB0);
    cudaGetSymbolAddress((void**)&dB1,   g_dB1);

    const size_t BH = (size_t)B * H;
    float* h0buf[2] = { st,          st + BH };
    float* c0      =   st + 2 * BH;
    float* h1buf[2] = { st + 3 * BH, st + 4 * BH };
    float* c1st    =   st + 5 * BH;

    // 0. weight interleaving + bias combine (runs inside graph; cheap)
    {
        int thr = 256;
        size_t nE = (size_t)G4 * E, nH = (size_t)G4 * H;
        interleave_w_kernel<<<(unsigned)((nE + thr - 1) / thr), thr>>>(e_Wih0, eWih0, E);
        interleave_w_kernel<<<(unsigned)((nH + thr - 1) / thr), thr>>>(e_Whh0, eWhh0, H);
        interleave_w_kernel<<<(unsigned)((nH + thr - 1) / thr), thr>>>(e_Wih1, eWih1, H);
        interleave_w_kernel<<<(unsigned)((nH + thr - 1) / thr), thr>>>(e_Whh1, eWhh1, H);
        interleave_w_kernel<<<(unsigned)((nE + thr - 1) / thr), thr>>>(d_Wih0, dWih0, E);
        interleave_w_kernel<<<(unsigned)((nH + thr - 1) / thr), thr>>>(d_Whh0, dWhh0, H);
        interleave_w_kernel<<<(unsigned)((nH + thr - 1) / thr), thr>>>(d_Wih1, dWih1, H);
        interleave_w_kernel<<<(unsigned)((nH + thr - 1) / thr), thr>>>(d_Whh1, dWhh1, H);
        combine_bias_kernel<<<(G4 + 255) / 256, 256>>>(e_bih0, e_bhh0, eB0);
        combine_bias_kernel<<<(G4 + 255) / 256, 256>>>(e_bih1, e_bhh1, eB1);
        combine_bias_kernel<<<(G4 + 255) / 256, 256>>>(d_bih0, d_bhh0, dB0);
        combine_bias_kernel<<<(G4 + 255) / 256, 256>>>(d_bih1, d_bhh1, dB1);
    }

    // 1. zero states
    {
        int n = 6 * B * H;
        zero_kernel<<<(n + 255) / 256, 256>>>(st, n);
    }

    // 2. transpose x_enc
    {
        size_t total = (size_t)B * T * E;
        transpose_bt_kernel<<<(unsigned)((total + 255) / 256), 256>>>(x_enc, xT);
    }

    // 3. encoder layer0 input precompute: pre = xT @ eWih0'^T  (interleaved)
    launch_plain(pre, G4, xT, E, E, eWih0, nullptr, T * B, G4, false);

    // 4. encoder layer0 recurrence (fused gate epilogue, h ping-pong)
    int ch0 = 0;
    for (int t = 0; t < T; ++t) {
        launch_lstm(h0buf[ch0], H, H, eWhh0, nullptr, 0, 0, nullptr,
                    eB0, pre + (size_t)t * B * G4, c0, h0buf[ch0 ^ 1],
                    ys + (size_t)t * BH);
        ch0 ^= 1;
    }

    // 5. encoder layer1 input precompute
    launch_plain(pre, G4, ys, H, H, eWih1, nullptr, T * B, G4, false);

    // 6. encoder layer1 recurrence
    int ch1 = 0;
    for (int t = 0; t < T; ++t) {
        launch_lstm(h1buf[ch1], H, H, eWhh1, nullptr, 0, 0, nullptr,
                    eB1, pre + (size_t)t * B * G4, c1st, h1buf[ch1 ^ 1], nullptr);
        ch1 ^= 1;
    }

    // 7. decoder initial input
    copy_last_kernel<<<(B * E + 255) / 256, 256>>>(x_enc, inp0);

    // 8. decoder autoregressive loop (3 kernels / step)
    for (int t = 0; t < P; ++t) {
        const float* inp = (t == 0) ? inp0 : (out + (size_t)(t - 1) * CC);
        const int lda_inp = (t == 0) ? E : (P * CC);

        // cell0
        launch_lstm(inp, lda_inp, E, dWih0, h0buf[ch0], H, H, dWhh0,
                    dB0, nullptr, c0, h0buf[ch0 ^ 1], nullptr);
        ch0 ^= 1;

        // cell1
        launch_lstm(h0buf[ch0], H, H, dWih1, h1buf[ch1], H, H, dWhh1,
                    dB1, nullptr, c1st, h1buf[ch1 ^ 1], nullptr);
        ch1 ^= 1;

        // fc
        launch_plain(out + (size_t)t * CC, P * CC, h1buf[ch1], H, H, fc_W,
                     fc_b, B, CC, true);
    }
}

// round 3
// speedup vs baseline: 1.8802x; 1.8802x over previous
#include <cuda_runtime.h>
#include <math.h>

// Problem constants
#define H   512
#define E   321
#define CC  321
#define T   96
#define P   96
#define B   512
#define G4  2048          // 4*H
#define EP  336           // E padded to mult of 16
#define NCP 384           // CC padded to mult of 64

// ---------------- scratch (device globals) -----------------------------------
__device__ float g_xTp[(size_t)T * B * EP];    // x_enc transposed+padded (T,B,EP)
__device__ float g_pre[(size_t)T * B * G4];    // batched x@Wih'^T (interleaved)
__device__ float g_ys[(size_t)T * B * H];      // enc layer0 outputs / dec h1 history
__device__ float g_state[6 * B * H];           // h0a,h0b,c0,h1a,h1b,c1
__device__ float g_inp0p[B * EP];              // decoder initial input (padded)

// interleaved weights: row (j*4+g) <- original row (g*H+j)
__device__ float g_eWih0p[G4 * EP];
__device__ float g_eWhh0[G4 * H];
__device__ float g_eWih1[G4 * H];
__device__ float g_eWhh1[G4 * H];
__device__ float g_dWih0p[G4 * EP];
__device__ float g_dWhh0[G4 * H];
__device__ float g_dWih1[G4 * H];
__device__ float g_dWhh1[G4 * H];
__device__ float g_Wfold[G4 * H];              // dWih0 @ fc_W (interleaved rows)
__device__ float g_fcWTp[H * EP];              // fc_W^T padded (H x EP)
__device__ float g_fcWp[NCP * H];              // fc_W padded to NCP rows
__device__ float g_eB0[G4], g_eB1[G4], g_dB0[G4], g_dB0f[G4], g_dB1[G4];
__device__ float g_fcbp[NCP];

// ---------------- setup kernels -----------------------------------------------
__global__ void interleave_pad_kernel(const float* __restrict__ src,
                                      float* __restrict__ dst, int K, int Kp)
{
    size_t idx = (size_t)blockIdx.x * blockDim.x + threadIdx.x;
    size_t total = (size_t)G4 * Kp;
    if (idx >= total) return;
    int np = (int)(idx / Kp);
    int k  = (int)(idx % Kp);
    int j = np >> 2, g = np & 3;
    dst[idx] = (k < K) ? src[((size_t)(g * H + j)) * K + k] : 0.f;
}

__global__ void combine_bias_kernel(const float* __restrict__ bih,
                                    const float* __restrict__ bhh,
                                    float* __restrict__ dst)
{
    int n = blockIdx.x * blockDim.x + threadIdx.x;
    if (n >= G4) return;
    int j = n >> 2, g = n & 3;
    dst[n] = bih[g * H + j] + bhh[g * H + j];
}

// dB0f[n] = dB0[n] + sum_c dWih0p[n,c]*fc_b[c]
__global__ void fold_bias_kernel(const float* __restrict__ Wp,
                                 const float* __restrict__ fcb,
                                 const float* __restrict__ dB0,
                                 float* __restrict__ out)
{
    int n = blockIdx.x * blockDim.x + threadIdx.x;
    if (n >= G4) return;
    float s = dB0[n];
    const float* row = Wp + (size_t)n * EP;
    for (int c = 0; c < CC; ++c) s += row[c] * fcb[c];
    out[n] = s;
}

// fcWTp[h, c] = fc_W[c, h] (padded c)
__global__ void fcwt_kernel(const float* __restrict__ fcW, float* __restrict__ dst)
{
    int idx = blockIdx.x * blockDim.x + threadIdx.x;
    if (idx >= H * EP) return;
    int h = idx / EP, c = idx % EP;
    dst[idx] = (c < CC) ? fcW[(size_t)c * H + h] : 0.f;
}

// fcWp[n, h] = fc_W[n, h] (padded n)
__global__ void fcwpad_kernel(const float* __restrict__ fcW, float* __restrict__ dst)
{
    int idx = blockIdx.x * blockDim.x + threadIdx.x;
    if (idx >= NCP * H) return;
    int n = idx / H, h = idx % H;
    dst[idx] = (n < CC) ? fcW[(size_t)n * H + h] : 0.f;
}

__global__ void fcbpad_kernel(const float* __restrict__ fcb, float* __restrict__ dst)
{
    int n = blockIdx.x * blockDim.x + threadIdx.x;
    if (n >= NCP) return;
    dst[n] = (n < CC) ? fcb[n] : 0.f;
}

__global__ void zero_kernel(float* p, int n)
{
    int i = blockIdx.x * blockDim.x + threadIdx.x;
    if (i < n) p[i] = 0.f;
}

// (B,T,E) -> (T,B,EP) zero-padded
__global__ void transpose_pad_kernel(const float* __restrict__ in, float* __restrict__ out)
{
    size_t idx = (size_t)blockIdx.x * blockDim.x + threadIdx.x;
    size_t total = (size_t)T * B * EP;
    if (idx >= total) return;
    int e = (int)(idx % EP);
    int b = (int)((idx / EP) % B);
    int t = (int)(idx / ((size_t)EP * B));
    out[idx] = (e < E) ? in[(size_t)b * T * E + (size_t)t * E + e] : 0.f;
}

__global__ void copy_last_pad_kernel(const float* __restrict__ x, float* __restrict__ out)
{
    int i = blockIdx.x * blockDim.x + threadIdx.x;
    if (i >= B * EP) return;
    int b = i / EP, e = i % EP;
    out[i] = (e < E) ? x[(size_t)b * T * E + (size_t)(T - 1) * E + e] : 0.f;
}

// ---------------- fast GEMM (64x64, 256 thr, double-buffered, no predicates) ---
// Requirements: M%64==0, N%64==0 (grid exact), K%16==0, lda%4==0, ldw%4==0.
// C[m,n] = sum_k A1[m,k]*W1[n,k] (+ A2[m,k]*W2[n,k])
// EPI=0: Cout[m,n] = acc (+bias[n])
// EPI=1: LSTM cell epilogue (interleaved gates; 4 cols/thread = 1 hidden unit)
// EPI=2: batched-fc scatter: row m=(t*B+b) -> out[b*P*CC + t*CC + n], n<Ncheck
__device__ __forceinline__ float sigmf(float x) { return 1.f / (1.f + __expf(-x)); }

template<int EPI>
__global__ __launch_bounds__(256)
void gemm_fast(float* __restrict__ Cout, int ldc,
               const float* __restrict__ A1, int lda1, int K1,
               const float* __restrict__ W1, int ldw1,
               const float* __restrict__ A2, int lda2, int K2,
               const float* __restrict__ W2, int ldw2,
               const float* __restrict__ bias,
               const float* __restrict__ pre,
               float* __restrict__ cst, float* __restrict__ hout,
               float* __restrict__ ysout, int Ncheck)
{
    __shared__ float As[2][16][68];
    __shared__ float Ws[2][16][68];

    const int bm = blockIdx.y * 64;
    const int bn = blockIdx.x * 64;
    const int tid = threadIdx.x;
    const int lm = tid >> 2;          // 0..63 (row of tile to load)
    const int lk = (tid & 3) * 4;     // 0,4,8,12
    const int tr = tid >> 4;          // 0..15
    const int tc = tid & 15;          // 0..15

    float acc[4][4];
#pragma unroll
    for (int i = 0; i < 4; ++i)
#pragma unroll
        for (int j = 0; j < 4; ++j) acc[i][j] = 0.f;

    for (int phase = 0; phase < 2; ++phase) {
        const float* A = phase ? A2 : A1;
        if (!A) continue;
        const float* W = phase ? W2 : W1;
        const int K   = phase ? K2 : K1;
        const int lda = phase ? lda2 : lda1;
        const int ldw = phase ? ldw2 : ldw1;
        const int nk  = K >> 4;

        const float* Aptr = A + (size_t)(bm + lm) * lda + lk;
        const float* Wptr = W + (size_t)(bn + lm) * ldw + lk;

        __syncthreads();   // smem may still be read by previous phase
        float4 pa = *(const float4*)Aptr;
        float4 pw = *(const float4*)Wptr;
        As[0][lk + 0][lm] = pa.x; As[0][lk + 1][lm] = pa.y;
        As[0][lk + 2][lm] = pa.z; As[0][lk + 3][lm] = pa.w;
        Ws[0][lk + 0][lm] = pw.x; Ws[0][lk + 1][lm] = pw.y;
        Ws[0][lk + 2][lm] = pw.z; Ws[0][lk + 3][lm] = pw.w;
        __syncthreads();

        int buf = 0;
        for (int it = 0; it < nk; ++it) {
            const bool more = (it + 1 < nk);
            if (more) {
                pa = *(const float4*)(Aptr + (it + 1) * 16);
                pw = *(const float4*)(Wptr + (it + 1) * 16);
            }
#pragma unroll
            for (int kk = 0; kk < 16; ++kk) {
                float4 a4 = *(const float4*)&As[buf][kk][tr * 4];
                float4 w4 = *(const float4*)&Ws[buf][kk][tc * 4];
                float av[4] = {a4.x, a4.y, a4.z, a4.w};
                float wv[4] = {w4.x, w4.y, w4.z, w4.w};
#pragma unroll
                for (int i = 0; i < 4; ++i)
#pragma unroll
                    for (int j = 0; j < 4; ++j)
                        acc[i][j] += av[i] * wv[j];
            }
            if (more) {
                const int nb = buf ^ 1;
                As[nb][lk + 0][lm] = pa.x; As[nb][lk + 1][lm] = pa.y;
                As[nb][lk + 2][lm] = pa.z; As[nb][lk + 3][lm] = pa.w;
                Ws[nb][lk + 0][lm] = pw.x; Ws[nb][lk + 1][lm] = pw.y;
                Ws[nb][lk + 2][lm] = pw.z; Ws[nb][lk + 3][lm] = pw.w;
                __syncthreads();
                buf = nb;
            }
        }
    }

    if (EPI == 0) {
#pragma unroll
        for (int i = 0; i < 4; ++i) {
            const int gm = bm + tr * 4 + i;
            const int gn = bn + tc * 4;
            float4 v;
            v.x = acc[i][0]; v.y = acc[i][1]; v.z = acc[i][2]; v.w = acc[i][3];
            if (bias) {
                const float4 b4 = *(const float4*)&bias[gn];
                v.x += b4.x; v.y += b4.y; v.z += b4.z; v.w += b4.w;
            }
            *(float4*)&Cout[(size_t)gm * ldc + gn] = v;
        }
    } else if (EPI == 1) {
        const int nb4 = bn + tc * 4;       // 4 gate cols of one hidden unit
        const int jh  = (bn >> 2) + tc;    // hidden index
        const float4 b4 = *(const float4*)&bias[nb4];
#pragma unroll
        for (int i = 0; i < 4; ++i) {
            const int gm = bm + tr * 4 + i;
            float gi = acc[i][0] + b4.x;
            float gf = acc[i][1] + b4.y;
            float gg = acc[i][2] + b4.z;
            float go = acc[i][3] + b4.w;
            if (pre) {
                const float4 p4 = *(const float4*)&pre[(size_t)gm * G4 + nb4];
                gi += p4.x; gf += p4.y; gg += p4.z; go += p4.w;
            }
            const size_t ci = (size_t)gm * H + jh;
            const float cv = sigmf(gf) * cst[ci] + sigmf(gi) * tanhf(gg);
            const float hv = sigmf(go) * tanhf(cv);
            cst[ci] = cv;
            hout[ci] = hv;
            if (ysout) ysout[ci] = hv;
        }
    } else { // EPI == 2
        const int gn0 = bn + tc * 4;
#pragma unroll
        for (int i = 0; i < 4; ++i) {
            const int gm = bm + tr * 4 + i;
            const int bb = gm & (B - 1);
            const int tt = gm >> 9;        // B = 512
            float* o = Cout + (size_t)bb * (P * CC) + (size_t)tt * CC;
#pragma unroll
            for (int j = 0; j < 4; ++j) {
                const int gn = gn0 + j;
                if (gn < Ncheck) o[gn] = acc[i][j] + bias[gn];
            }
        }
    }
}

// ---------------- launch helpers -----------------------------------------------
static inline void launch_lstm(const float* A1, int lda1, int K1, const float* W1, int ldw1,
                               const float* A2, int lda2, int K2, const float* W2, int ldw2,
                               const float* bias, const float* pre,
                               float* cst, float* hout, float* ysout)
{
    dim3 grid(G4 / 64, B / 64);
    gemm_fast<1><<<grid, 256>>>(nullptr, 0, A1, lda1, K1, W1, ldw1,
                                A2, lda2, K2, W2, ldw2,
                                bias, pre, cst, hout, ysout, 0);
}

static inline void launch_plain(float* Cp, int ldc,
                                const float* A, int lda, int K,
                                const float* W, int ldw,
                                const float* bias, int M, int N)
{
    dim3 grid(N / 64, M / 64);
    gemm_fast<0><<<grid, 256>>>(Cp, ldc, A, lda, K, W, ldw,
                                nullptr, 0, 0, nullptr, 0,
                                bias, nullptr, nullptr, nullptr, nullptr, 0);
}

// ---------------- entry ----------------------------------------------------------
extern "C" void kernel_launch(void* const* d_in, const int* in_sizes, int n_in,
                              void* d_out, int out_size)
{
    const float* x_enc  = (const float*)d_in[0];
    const float* e_Wih0 = (const float*)d_in[4];
    const float* e_Whh0 = (const float*)d_in[5];
    const float* e_bih0 = (const float*)d_in[6];
    const float* e_bhh0 = (const float*)d_in[7];
    const float* e_Wih1 = (const float*)d_in[8];
    const float* e_Whh1 = (const float*)d_in[9];
    const float* e_bih1 = (const float*)d_in[10];
    const float* e_bhh1 = (const float*)d_in[11];
    const float* d_Wih0 = (const float*)d_in[12];
    const float* d_Whh0 = (const float*)d_in[13];
    const float* d_bih0 = (const float*)d_in[14];
    const float* d_bhh0 = (const float*)d_in[15];
    const float* d_Wih1 = (const float*)d_in[16];
    const float* d_Whh1 = (const float*)d_in[17];
    const float* d_bih1 = (const float*)d_in[18];
    const float* d_bhh1 = (const float*)d_in[19];
    const float* fc_W   = (const float*)d_in[20];
    const float* fc_b   = (const float*)d_in[21];
    float* out = (float*)d_out;

    float *xTp, *pre, *ys, *st, *inp0p;
    float *eWih0p, *eWhh0, *eWih1, *eWhh1, *dWih0p, *dWhh0, *dWih1, *dWhh1;
    float *Wfold, *fcWTp, *fcWp, *eB0, *eB1, *dB0, *dB0f, *dB1, *fcbp;
    cudaGetSymbolAddress((void**)&xTp,    g_xTp);
    cudaGetSymbolAddress((void**)&pre,    g_pre);
    cudaGetSymbolAddress((void**)&ys,     g_ys);
    cudaGetSymbolAddress((void**)&st,     g_state);
    cudaGetSymbolAddress((void**)&inp0p,  g_inp0p);
    cudaGetSymbolAddress((void**)&eWih0p, g_eWih0p);
    cudaGetSymbolAddress((void**)&eWhh0,  g_eWhh0);
    cudaGetSymbolAddress((void**)&eWih1,  g_eWih1);
    cudaGetSymbolAddress((void**)&eWhh1,  g_eWhh1);
    cudaGetSymbolAddress((void**)&dWih0p, g_dWih0p);
    cudaGetSymbolAddress((void**)&dWhh0,  g_dWhh0);
    cudaGetSymbolAddress((void**)&dWih1,  g_dWih1);
    cudaGetSymbolAddress((void**)&dWhh1,  g_dWhh1);
    cudaGetSymbolAddress((void**)&Wfold,  g_Wfold);
    cudaGetSymbolAddress((void**)&fcWTp,  g_fcWTp);
    cudaGetSymbolAddress((void**)&fcWp,   g_fcWp);
    cudaGetSymbolAddress((void**)&eB0,    g_eB0);
    cudaGetSymbolAddress((void**)&eB1,    g_eB1);
    cudaGetSymbolAddress((void**)&dB0,    g_dB0);
    cudaGetSymbolAddress((void**)&dB0f,   g_dB0f);
    cudaGetSymbolAddress((void**)&dB1,    g_dB1);
    cudaGetSymbolAddress((void**)&fcbp,   g_fcbp);

    const size_t BH = (size_t)B * H;
    float* h0buf[2] = { st,          st + BH };
    float* c0      =   st + 2 * BH;
    float* h1buf[2] = { st + 3 * BH, st + 4 * BH };
    float* c1st    =   st + 5 * BH;

    const int thr = 256;

    // ---- setup: weight interleave (+pad), bias combine, fc pads, fold ----
    {
        size_t nEp = (size_t)G4 * EP, nH = (size_t)G4 * H;
        interleave_pad_kernel<<<(unsigned)((nEp + thr - 1) / thr), thr>>>(e_Wih0, eWih0p, E, EP);
        interleave_pad_kernel<<<(unsigned)((nH + thr - 1) / thr), thr>>>(e_Whh0, eWhh0, H, H);
        interleave_pad_kernel<<<(unsigned)((nH + thr - 1) / thr), thr>>>(e_Wih1, eWih1, H, H);
        interleave_pad_kernel<<<(unsigned)((nH + thr - 1) / thr), thr>>>(e_Whh1, eWhh1, H, H);
        interleave_pad_kernel<<<(unsigned)((nEp + thr - 1) / thr), thr>>>(d_Wih0, dWih0p, E, EP);
        interleave_pad_kernel<<<(unsigned)((nH + thr - 1) / thr), thr>>>(d_Whh0, dWhh0, H, H);
        interleave_pad_kernel<<<(unsigned)((nH + thr - 1) / thr), thr>>>(d_Wih1, dWih1, H, H);
        interleave_pad_kernel<<<(unsigned)((nH + thr - 1) / thr), thr>>>(d_Whh1, dWhh1, H, H);
        combine_bias_kernel<<<(G4 + thr - 1) / thr, thr>>>(e_bih0, e_bhh0, eB0);
        combine_bias_kernel<<<(G4 + thr - 1) / thr, thr>>>(e_bih1, e_bhh1, eB1);
        combine_bias_kernel<<<(G4 + thr - 1) / thr, thr>>>(d_bih0, d_bhh0, dB0);
        combine_bias_kernel<<<(G4 + thr - 1) / thr, thr>>>(d_bih1, d_bhh1, dB1);
        fcwt_kernel<<<(H * EP + thr - 1) / thr, thr>>>(fc_W, fcWTp);
        fcwpad_kernel<<<(NCP * H + thr - 1) / thr, thr>>>(fc_W, fcWp);
        fcbpad_kernel<<<(NCP + thr - 1) / thr, thr>>>(fc_b, fcbp);
        // Wfold = dWih0p @ fcWTp^T : (G4 x H), K=EP
        launch_plain(Wfold, H, dWih0p, EP, EP, fcWTp, EP, nullptr, G4, H);
        fold_bias_kernel<<<(G4 + thr - 1) / thr, thr>>>(dWih0p, fc_b, dB0, dB0f);
    }

    // ---- zero states ----
    zero_kernel<<<(6 * B * H + thr - 1) / thr, thr>>>(st, 6 * B * H);

    // ---- transpose+pad x_enc ----
    {
        size_t total = (size_t)T * B * EP;
        transpose_pad_kernel<<<(unsigned)((total + thr - 1) / thr), thr>>>(x_enc, xTp);
    }

    // ---- encoder layer0 batched input GEMM ----
    launch_plain(pre, G4, xTp, EP, EP, eWih0p, EP, nullptr, T * B, G4);

    // ---- encoder layer0 recurrence ----
    int ch0 = 0;
    for (int t = 0; t < T; ++t) {
        launch_lstm(h0buf[ch0], H, H, eWhh0, H, nullptr, 0, 0, nullptr, 0,
                    eB0, pre + (size_t)t * B * G4, c0, h0buf[ch0 ^ 1],
                    ys + (size_t)t * BH);
        ch0 ^= 1;
    }

    // ---- encoder layer1 batched input GEMM ----
    launch_plain(pre, G4, ys, H, H, eWih1, H, nullptr, T * B, G4);

    // ---- encoder layer1 recurrence ----
    int ch1 = 0;
    for (int t = 0; t < T; ++t) {
        launch_lstm(h1buf[ch1], H, H, eWhh1, H, nullptr, 0, 0, nullptr, 0,
                    eB1, pre + (size_t)t * B * G4, c1st, h1buf[ch1 ^ 1], nullptr);
        ch1 ^= 1;
    }

    // ---- decoder initial input ----
    copy_last_pad_kernel<<<(B * EP + thr - 1) / thr, thr>>>(x_enc, inp0p);

    // ---- decoder recurrence (fc folded into cell0; h1 history -> g_ys) ----
    for (int t = 0; t < P; ++t) {
        if (t == 0) {
            launch_lstm(inp0p, EP, EP, dWih0p, EP,
                        h0buf[ch0], H, H, dWhh0, H,
                        dB0, nullptr, c0, h0buf[ch0 ^ 1], nullptr);
        } else {
            launch_lstm(h1buf[ch1], H, H, Wfold, H,
                        h0buf[ch0], H, H, dWhh0, H,
                        dB0f, nullptr, c0, h0buf[ch0 ^ 1], nullptr);
        }
        ch0 ^= 1;

        launch_lstm(h0buf[ch0], H, H, dWih1, H,
                    h1buf[ch1], H, H, dWhh1, H,
                    dB1, nullptr, c1st, h1buf[ch1 ^ 1],
                    ys + (size_t)t * BH);
        ch1 ^= 1;
    }

    // ---- batched final fc: out[b,t,:] = h1_hist[t,b,:] @ fc_W^T + fc_b ----
    {
        dim3 grid(NCP / 64, (T * B) / 64);
        gemm_fast<2><<<grid, 256>>>(out, 0, ys, H, H, fcWp, H,
                                    nullptr, 0, 0, nullptr, 0,
                                    fcbp, nullptr, nullptr, nullptr, nullptr, CC);
    }
}